// round 2
// baseline (speedup 1.0000x reference)
#include <cuda_runtime.h>
#include <cstdint>
#include <cstddef>

#define GF      64
#define EXP_N   8
#define TILE    128
#define ROWP    68          // 64 + 4 pad: conflict-free smem rows (scalar & float4)
#define NPTS_MAX 262144

// ---------------- scratch (no allocations allowed) ----------------
__device__ float g_feat[(size_t)NPTS_MAX * GF];       // gated features [N,64]
__device__ int   g_list[(size_t)EXP_N * NPTS_MAX];    // per-expert point lists
__device__ int   g_cnt[EXP_N];                        // per-expert counts

// ---------------- smem layouts (floats) ----------------
// gate kernel: W(4096) + staging A(128*68) + consts
#define G_OFF_W    0
#define G_OFF_A    (G_OFF_W + GF*GF)
#define G_OFF_FW   (G_OFF_A + TILE*ROWP)
#define G_OFF_FB   (G_OFF_FW + GF*3)
#define G_OFF_GB1  (G_OFF_FB + GF)
#define G_OFF_LNG  (G_OFF_GB1 + GF)
#define G_OFF_LNB  (G_OFF_LNG + GF)
#define G_OFF_GW2  (G_OFF_LNB + GF)
#define G_OFF_GB2  (G_OFF_GW2 + EXP_N*GF)
#define G_SMEM_FLOATS (G_OFF_GB2 + EXP_N)
#define G_SMEM_BYTES  (G_SMEM_FLOATS * 4)

// expert kernel: W(4096) + gather buf(128*68) + consts
#define E_OFF_W    0
#define E_OFF_B0   (E_OFF_W + GF*GF)
#define E_OFF_SB   (E_OFF_B0 + TILE*ROWP)
#define E_OFF_WL   (E_OFF_SB + GF)
#define E_OFF_BL   (E_OFF_WL + GF)
#define E_OFF_ID   (E_OFF_BL + 1)
#define E_SMEM_FLOATS (E_OFF_ID + TILE)
#define E_SMEM_BYTES  (E_SMEM_FLOATS * 4)

// ---------------- register-resident 64x64 matvec ----------------
// a[] lives in registers (fully unrolled indices). sW is smem, warp-broadcast.
// out[] written to registers.
__device__ __forceinline__ void matvec64_rr(const float* __restrict__ sW,
                                            const float* __restrict__ bias,
                                            const float* __restrict__ a,   // [64] regs
                                            float* __restrict__ o)         // [64] regs
{
#pragma unroll
    for (int k = 0; k < GF; k += 4) {
        float a0 = bias[k + 0];
        float a1 = bias[k + 1];
        float a2 = bias[k + 2];
        float a3 = bias[k + 3];
        const float4* w0 = (const float4*)&sW[(k + 0) * GF];
        const float4* w1 = (const float4*)&sW[(k + 1) * GF];
        const float4* w2 = (const float4*)&sW[(k + 2) * GF];
        const float4* w3 = (const float4*)&sW[(k + 3) * GF];
#pragma unroll
        for (int j = 0; j < GF / 4; j++) {
            const float x0 = a[4*j], x1 = a[4*j+1], x2 = a[4*j+2], x3 = a[4*j+3];
            float4 q;
            q = w0[j]; a0 = fmaf(x0,q.x, fmaf(x1,q.y, fmaf(x2,q.z, fmaf(x3,q.w, a0))));
            q = w1[j]; a1 = fmaf(x0,q.x, fmaf(x1,q.y, fmaf(x2,q.z, fmaf(x3,q.w, a1))));
            q = w2[j]; a2 = fmaf(x0,q.x, fmaf(x1,q.y, fmaf(x2,q.z, fmaf(x3,q.w, a2))));
            q = w3[j]; a3 = fmaf(x0,q.x, fmaf(x1,q.y, fmaf(x2,q.z, fmaf(x3,q.w, a3))));
        }
        o[k + 0] = a0;
        o[k + 1] = a1;
        o[k + 2] = a2;
        o[k + 3] = a3;
    }
}

// ---------------- kernels ----------------
__global__ void init_kernel(float* __restrict__ out, int total)
{
    int i = blockIdx.x * blockDim.x + threadIdx.x;
    if (i < total) out[i] = 0.0f;
    if (i < EXP_N) g_cnt[i] = 0;
}

__global__ void __launch_bounds__(TILE) gate_kernel(
    const float* __restrict__ coords, const float* __restrict__ fw,
    const float* __restrict__ fb,     const float* __restrict__ gw1,
    const float* __restrict__ gb1,    const float* __restrict__ lng,
    const float* __restrict__ lnb,    const float* __restrict__ gw2,
    const float* __restrict__ gb2,    int n)
{
    extern __shared__ float dsm[];
    float* sW   = dsm + G_OFF_W;
    float (*sA)[ROWP] = (float(*)[ROWP])(dsm + G_OFF_A);
    float* sfw  = dsm + G_OFF_FW;
    float* sfb  = dsm + G_OFF_FB;
    float* sgb1 = dsm + G_OFF_GB1;
    float* slng = dsm + G_OFF_LNG;
    float* slnb = dsm + G_OFF_LNB;
    float* sgw2 = dsm + G_OFF_GW2;
    float* sgb2 = dsm + G_OFF_GB2;

    const int tid  = threadIdx.x;
    const int base = blockIdx.x * TILE;

    for (int i = tid; i < GF * GF; i += TILE) sW[i] = gw1[i];
    for (int i = tid; i < GF * 3;  i += TILE) sfw[i] = fw[i];
    for (int i = tid; i < GF;      i += TILE) {
        sfb[i]  = fb[i];  sgb1[i] = gb1[i];
        slng[i] = lng[i]; slnb[i] = lnb[i];
    }
    for (int i = tid; i < EXP_N * GF; i += TILE) sgw2[i] = gw2[i];
    if (tid < EXP_N) sgb2[tid] = gb2[tid];

    const int p   = base + tid;
    const bool act = (p < n);
    float c0 = 0.f, c1 = 0.f, c2 = 0.f;
    if (act) { c0 = coords[3*p]; c1 = coords[3*p+1]; c2 = coords[3*p+2]; }
    __syncthreads();

    // feature = coords @ fw^T + fb  (registers + smem staging for coalesced store)
    float f[GF];
#pragma unroll
    for (int k = 0; k < GF; k++) {
        f[k] = sfb[k] + c0*sfw[3*k] + c1*sfw[3*k+1] + c2*sfw[3*k+2];
        sA[tid][k] = f[k];
    }
    __syncthreads();

    // coalesced feature writeback
    {
        int nrows = n - base; if (nrows > TILE) nrows = TILE;
        if (nrows > 0) {
            for (int idx = tid; idx < nrows * GF; idx += TILE) {
                int r = idx >> 6, k = idx & 63;
                g_feat[(size_t)base * GF + idx] = sA[r][k];
            }
        }
    }

    // g = feature @ gw1^T + gb1  (registers)
    float g[GF];
    matvec64_rr(sW, sgb1, f, g);

    // LayerNorm (biased var, eps=1e-5)
    float mu = 0.f;
#pragma unroll
    for (int j = 0; j < GF; j++) mu += g[j];
    mu *= (1.0f / GF);
    float var = 0.f;
#pragma unroll
    for (int j = 0; j < GF; j++) { float d = g[j] - mu; var += d * d; }
    var *= (1.0f / GF);
    const float inv = rsqrtf(var + 1e-5f);
#pragma unroll
    for (int j = 0; j < GF; j++)
        g[j] = (g[j] - mu) * inv * slng[j] + slnb[j];

    // logits = gn @ gw2^T + gb2 ; top-2 selection on logits (softmax is monotonic)
    float lg[EXP_N];
#pragma unroll
    for (int e = 0; e < EXP_N; e++) {
        float acc = sgb2[e];
#pragma unroll
        for (int j = 0; j < GF; j++) acc += sgw2[e * GF + j] * g[j];
        lg[e] = acc;
    }
    float m1 = -1e30f, m2 = -1e30f;
#pragma unroll
    for (int e = 0; e < EXP_N; e++) {
        float v = lg[e];
        if (v > m1)      { m2 = m1; m1 = v; }
        else if (v > m2) { m2 = v; }
    }

    // warp-aggregated scatter into per-expert lists
    const int lane = tid & 31;
#pragma unroll
    for (int e = 0; e < EXP_N; e++) {
        bool sel = act && (lg[e] >= m2);
        unsigned bm = __ballot_sync(0xffffffffu, sel);
        if (bm) {
            int leader = __ffs(bm) - 1;
            int pos = 0;
            if (lane == leader) pos = atomicAdd(&g_cnt[e], __popc(bm));
            pos = __shfl_sync(0xffffffffu, pos, leader);
            if (sel) {
                int off = pos + __popc(bm & ((1u << lane) - 1u));
                g_list[(size_t)e * NPTS_MAX + off] = p;
            }
        }
    }
}

__global__ void __launch_bounds__(TILE) expert_kernel(
    const float* __restrict__ we0, const float* __restrict__ be0,
    const float* __restrict__ wm,  const float* __restrict__ bm,
    const float* __restrict__ wl,  const float* __restrict__ bl,
    float* __restrict__ out, int n)
{
    extern __shared__ float dsm[];
    float* sW = dsm + E_OFF_W;
    float (*buf0)[ROWP] = (float(*)[ROWP])(dsm + E_OFF_B0);
    float* sb  = dsm + E_OFF_SB;
    float* swl = dsm + E_OFF_WL;
    float* sbl = dsm + E_OFF_BL;
    int*   sId = (int*)(dsm + E_OFF_ID);

    const int e    = blockIdx.y;
    const int cnt  = g_cnt[e];
    const int base = blockIdx.x * TILE;
    if (base >= cnt) return;
    int nrows = cnt - base; if (nrows > TILE) nrows = TILE;
    const int tid = threadIdx.x;

    if (tid < nrows) sId[tid] = g_list[(size_t)e * NPTS_MAX + base + tid];
    __syncthreads();

    // coalesced gather of feature rows into smem
    {
        const int lane = tid & 31, w = tid >> 5;
        for (int r = w; r < nrows; r += TILE / 32) {
            const float* src = &g_feat[(size_t)sId[r] * GF];
            buf0[r][lane]      = src[lane];
            buf0[r][lane + 32] = src[lane + 32];
        }
    }
    __syncthreads();

    // pull this thread's row into registers; activations stay in regs across layers
    float a[GF];
    if (tid < nrows) {
#pragma unroll
        for (int k = 0; k < GF; k++) a[k] = buf0[tid][k];
    }

#pragma unroll 1
    for (int layer = 0; layer < 3; layer++) {
        const float* wp; const float* bp; float freq;
        if (layer == 0) {
            wp = we0 + (size_t)e * GF * GF;
            bp = be0 + e * GF;
            freq = 22.5f + 45.0f * (float)e;        // W0S[e]
        } else {
            wp = wm + ((size_t)(layer - 1) * EXP_N + e) * GF * GF;
            bp = bm + ((size_t)(layer - 1) * EXP_N + e) * GF;
            freq = 30.0f;
        }
        __syncthreads();   // prior layer done reading sW
        for (int i = tid; i < GF * GF; i += TILE) sW[i] = wp[i];
        if (tid < GF) sb[tid] = bp[tid];
        __syncthreads();

        if (tid < nrows) {
            float o[GF];
            matvec64_rr(sW, sb, a, o);
#pragma unroll
            for (int k = 0; k < GF; k++) a[k] = __sinf(freq * o[k]);
        }
    }

    __syncthreads();
    if (tid < GF) swl[tid] = wl[e * GF + tid];
    if (tid == 0) sbl[0] = bl[e];
    __syncthreads();

    if (tid < nrows) {
        float acc = sbl[0];
#pragma unroll
        for (int j = 0; j < GF; j++) acc += swl[j] * a[j];
        atomicAdd(&out[sId[tid]], acc);
    }
}

__global__ void aux_kernel(float* __restrict__ out, int n, int out_size)
{
    if (threadIdx.x == 0 && blockIdx.x == 0) {
        long long s = 0;
#pragma unroll
        for (int e = 0; e < EXP_N; e++) {
            long long c = (long long)g_cnt[e];
            s += c * c;
        }
        double aux = (double)EXP_N * (double)s / ((double)n * (double)n);
        if (out_size > n) out[n] = (float)aux;
    }
}

// ---------------- launcher ----------------
extern "C" void kernel_launch(void* const* d_in, const int* in_sizes, int n_in,
                              void* d_out, int out_size)
{
    const float* coords = (const float*)d_in[0];
    const float* fw   = (const float*)d_in[1];
    const float* fb   = (const float*)d_in[2];
    const float* gw1  = (const float*)d_in[3];
    const float* gb1  = (const float*)d_in[4];
    const float* ln_g = (const float*)d_in[5];
    const float* ln_b = (const float*)d_in[6];
    const float* gw2  = (const float*)d_in[7];
    const float* gb2  = (const float*)d_in[8];
    const float* we0  = (const float*)d_in[9];
    const float* be0  = (const float*)d_in[10];
    const float* wm   = (const float*)d_in[11];
    const float* bm   = (const float*)d_in[12];
    const float* wl   = (const float*)d_in[13];
    const float* bl   = (const float*)d_in[14];
    float* out = (float*)d_out;

    const int n = in_sizes[0] / 3;
    const int ntiles = (n + TILE - 1) / TILE;

    cudaFuncSetAttribute(gate_kernel,   cudaFuncAttributeMaxDynamicSharedMemorySize, G_SMEM_BYTES);
    cudaFuncSetAttribute(expert_kernel, cudaFuncAttributeMaxDynamicSharedMemorySize, E_SMEM_BYTES);

    init_kernel<<<(out_size + 255) / 256, 256>>>(out, out_size);

    gate_kernel<<<ntiles, TILE, G_SMEM_BYTES>>>(coords, fw, fb, gw1, gb1,
                                                ln_g, ln_b, gw2, gb2, n);

    dim3 eg(ntiles, EXP_N);
    expert_kernel<<<eg, TILE, E_SMEM_BYTES>>>(we0, be0, wm, bm, wl, bl, out, n);

    aux_kernel<<<1, 32>>>(out, n, out_size);
}

// round 3
// speedup vs baseline: 1.1456x; 1.1456x over previous
#include <cuda_runtime.h>
#include <cstdint>
#include <cstddef>

#define GF      64
#define EXP_N   8
#define TILE    128
#define ROWP    68          // 64+4 pad: conflict-free for column access AND per-lane-row float4
#define NPTS_MAX 262144

// ---------------- scratch (no allocations allowed) ----------------
__device__ float g_feat[(size_t)NPTS_MAX * GF];       // gated features [N,64]
__device__ int   g_list[(size_t)EXP_N * NPTS_MAX];    // per-expert point lists
__device__ int   g_cnt[EXP_N];                        // per-expert counts (zeroed at end of aux)

// ---------------- smem layouts (floats) ----------------
// gate kernel
#define G_OFF_W    0
#define G_OFF_A    (G_OFF_W + GF*GF)
#define G_OFF_FW   (G_OFF_A + TILE*ROWP)
#define G_OFF_FB   (G_OFF_FW + GF*3)
#define G_OFF_GB1  (G_OFF_FB + GF)
#define G_OFF_LNG  (G_OFF_GB1 + GF)
#define G_OFF_LNB  (G_OFF_LNG + GF)
#define G_OFF_GW2  (G_OFF_LNB + GF)
#define G_OFF_GB2  (G_OFF_GW2 + EXP_N*GF)
#define G_SMEM_FLOATS (G_OFF_GB2 + EXP_N)
#define G_SMEM_BYTES  (G_SMEM_FLOATS * 4)

// expert kernel
#define E_OFF_W    0
#define E_OFF_B0   (E_OFF_W + GF*GF)
#define E_OFF_SB   (E_OFF_B0 + TILE*ROWP)
#define E_OFF_WL   (E_OFF_SB + GF)
#define E_OFF_BL   (E_OFF_WL + GF)
#define E_OFF_ID   (E_OFF_BL + 1)
#define E_SMEM_FLOATS (E_OFF_ID + TILE)
#define E_SMEM_BYTES  (E_SMEM_FLOATS * 4)

// ---------------- fused layer: regs -> (matvec, sin) -> smem row -> regs ----------------
// a[64] in registers (input, overwritten with result). srow = this thread's private
// smem row (16B aligned: ROWP*4 = 272 = 16*17). Outputs staged per 4-group to smem
// to keep peak register pressure ~a[64]+acc instead of a[64]+o[64].
__device__ __forceinline__ void layer64(const float* __restrict__ sW,
                                        const float* __restrict__ bias,
                                        float* __restrict__ a,       // [64] regs, in/out
                                        float* __restrict__ srow,    // smem, private row
                                        float freq)
{
#pragma unroll
    for (int k = 0; k < GF; k += 4) {
        float a0 = bias[k + 0];
        float a1 = bias[k + 1];
        float a2 = bias[k + 2];
        float a3 = bias[k + 3];
        const float4* w0 = (const float4*)&sW[(k + 0) * GF];
        const float4* w1 = (const float4*)&sW[(k + 1) * GF];
        const float4* w2 = (const float4*)&sW[(k + 2) * GF];
        const float4* w3 = (const float4*)&sW[(k + 3) * GF];
#pragma unroll
        for (int j = 0; j < GF / 4; j++) {
            const float x0 = a[4*j], x1 = a[4*j+1], x2 = a[4*j+2], x3 = a[4*j+3];
            float4 q;
            q = w0[j]; a0 = fmaf(x0,q.x, fmaf(x1,q.y, fmaf(x2,q.z, fmaf(x3,q.w, a0))));
            q = w1[j]; a1 = fmaf(x0,q.x, fmaf(x1,q.y, fmaf(x2,q.z, fmaf(x3,q.w, a1))));
            q = w2[j]; a2 = fmaf(x0,q.x, fmaf(x1,q.y, fmaf(x2,q.z, fmaf(x3,q.w, a2))));
            q = w3[j]; a3 = fmaf(x0,q.x, fmaf(x1,q.y, fmaf(x2,q.z, fmaf(x3,q.w, a3))));
        }
        float4 r;
        r.x = __sinf(freq * a0);
        r.y = __sinf(freq * a1);
        r.z = __sinf(freq * a2);
        r.w = __sinf(freq * a3);
        *(float4*)&srow[k] = r;     // same-thread smem: program-ordered, no sync needed
    }
#pragma unroll
    for (int k = 0; k < GF; k += 4) {
        float4 v = *(const float4*)&srow[k];
        a[k+0] = v.x; a[k+1] = v.y; a[k+2] = v.z; a[k+3] = v.w;
    }
}

// matvec only (no sin), staged through smem row the same way
__device__ __forceinline__ void matvec64_stage(const float* __restrict__ sW,
                                               const float* __restrict__ bias,
                                               const float* __restrict__ a,  // [64] regs
                                               float* __restrict__ srow)     // smem out
{
#pragma unroll
    for (int k = 0; k < GF; k += 4) {
        float a0 = bias[k + 0];
        float a1 = bias[k + 1];
        float a2 = bias[k + 2];
        float a3 = bias[k + 3];
        const float4* w0 = (const float4*)&sW[(k + 0) * GF];
        const float4* w1 = (const float4*)&sW[(k + 1) * GF];
        const float4* w2 = (const float4*)&sW[(k + 2) * GF];
        const float4* w3 = (const float4*)&sW[(k + 3) * GF];
#pragma unroll
        for (int j = 0; j < GF / 4; j++) {
            const float x0 = a[4*j], x1 = a[4*j+1], x2 = a[4*j+2], x3 = a[4*j+3];
            float4 q;
            q = w0[j]; a0 = fmaf(x0,q.x, fmaf(x1,q.y, fmaf(x2,q.z, fmaf(x3,q.w, a0))));
            q = w1[j]; a1 = fmaf(x0,q.x, fmaf(x1,q.y, fmaf(x2,q.z, fmaf(x3,q.w, a1))));
            q = w2[j]; a2 = fmaf(x0,q.x, fmaf(x1,q.y, fmaf(x2,q.z, fmaf(x3,q.w, a2))));
            q = w3[j]; a3 = fmaf(x0,q.x, fmaf(x1,q.y, fmaf(x2,q.z, fmaf(x3,q.w, a3))));
        }
        float4 r; r.x = a0; r.y = a1; r.z = a2; r.w = a3;
        *(float4*)&srow[k] = r;
    }
}

// ---------------- kernels ----------------
__global__ void __launch_bounds__(TILE, 3) gate_kernel(
    const float* __restrict__ coords, const float* __restrict__ fw,
    const float* __restrict__ fb,     const float* __restrict__ gw1,
    const float* __restrict__ gb1,    const float* __restrict__ lng,
    const float* __restrict__ lnb,    const float* __restrict__ gw2,
    const float* __restrict__ gb2,    float* __restrict__ out, int n)
{
    extern __shared__ float dsm[];
    float* sW   = dsm + G_OFF_W;
    float (*sA)[ROWP] = (float(*)[ROWP])(dsm + G_OFF_A);
    float* sfw  = dsm + G_OFF_FW;
    float* sfb  = dsm + G_OFF_FB;
    float* sgb1 = dsm + G_OFF_GB1;
    float* slng = dsm + G_OFF_LNG;
    float* slnb = dsm + G_OFF_LNB;
    float* sgw2 = dsm + G_OFF_GW2;
    float* sgb2 = dsm + G_OFF_GB2;

    const int tid  = threadIdx.x;
    const int base = blockIdx.x * TILE;

    for (int i = tid; i < GF * GF; i += TILE) sW[i] = gw1[i];
    for (int i = tid; i < GF * 3;  i += TILE) sfw[i] = fw[i];
    for (int i = tid; i < GF;      i += TILE) {
        sfb[i]  = fb[i];  sgb1[i] = gb1[i];
        slng[i] = lng[i]; slnb[i] = lnb[i];
    }
    for (int i = tid; i < EXP_N * GF; i += TILE) sgw2[i] = gw2[i];
    if (tid < EXP_N) sgb2[tid] = gb2[tid];

    const int p   = base + tid;
    const bool act = (p < n);
    float c0 = 0.f, c1 = 0.f, c2 = 0.f;
    if (act) { c0 = coords[3*p]; c1 = coords[3*p+1]; c2 = coords[3*p+2]; }
    if (act) out[p] = 0.0f;          // init fused here (expert adds later, stream-ordered)
    __syncthreads();

    // feature = coords @ fw^T + fb : regs + smem staging for coalesced store
    float a[GF];
#pragma unroll
    for (int k = 0; k < GF; k++) {
        a[k] = sfb[k] + c0*sfw[3*k] + c1*sfw[3*k+1] + c2*sfw[3*k+2];
        sA[tid][k] = a[k];
    }
    __syncthreads();

    // coalesced feature writeback
    {
        int nrows = n - base; if (nrows > TILE) nrows = TILE;
        if (nrows > 0) {
            for (int idx = tid; idx < nrows * GF; idx += TILE) {
                int r = idx >> 6, k = idx & 63;
                g_feat[(size_t)base * GF + idx] = sA[r][k];
            }
        }
    }
    __syncthreads();   // sA about to be reused as per-thread staging

    // g = feature @ gw1^T + gb1, staged into this thread's sA row
    matvec64_stage(sW, sgb1, a, sA[tid]);

    // reload g into regs (a dead), LayerNorm two-pass
#pragma unroll
    for (int k = 0; k < GF; k += 4) {
        float4 v = *(const float4*)&sA[tid][k];
        a[k+0] = v.x; a[k+1] = v.y; a[k+2] = v.z; a[k+3] = v.w;
    }
    float mu = 0.f;
#pragma unroll
    for (int j = 0; j < GF; j++) mu += a[j];
    mu *= (1.0f / GF);
    float var = 0.f;
#pragma unroll
    for (int j = 0; j < GF; j++) { float d = a[j] - mu; var += d * d; }
    var *= (1.0f / GF);
    const float inv = rsqrtf(var + 1e-5f);
#pragma unroll
    for (int j = 0; j < GF; j++)
        a[j] = (a[j] - mu) * inv * slng[j] + slnb[j];

    // logits + top-2 on logits (softmax monotonic)
    float lg[EXP_N];
#pragma unroll
    for (int e = 0; e < EXP_N; e++) {
        float acc = sgb2[e];
#pragma unroll
        for (int j = 0; j < GF; j++) acc += sgw2[e * GF + j] * a[j];
        lg[e] = acc;
    }
    float m1 = -1e30f, m2 = -1e30f;
#pragma unroll
    for (int e = 0; e < EXP_N; e++) {
        float v = lg[e];
        if (v > m1)      { m2 = m1; m1 = v; }
        else if (v > m2) { m2 = v; }
    }

    // warp-aggregated scatter into per-expert lists
    const int lane = tid & 31;
#pragma unroll
    for (int e = 0; e < EXP_N; e++) {
        bool sel = act && (lg[e] >= m2);
        unsigned bm = __ballot_sync(0xffffffffu, sel);
        if (bm) {
            int leader = __ffs(bm) - 1;
            int pos = 0;
            if (lane == leader) pos = atomicAdd(&g_cnt[e], __popc(bm));
            pos = __shfl_sync(0xffffffffu, pos, leader);
            if (sel) {
                int off = pos + __popc(bm & ((1u << lane) - 1u));
                g_list[(size_t)e * NPTS_MAX + off] = p;
            }
        }
    }
}

__global__ void __launch_bounds__(TILE, 3) expert_kernel(
    const float* __restrict__ we0, const float* __restrict__ be0,
    const float* __restrict__ wm,  const float* __restrict__ bm,
    const float* __restrict__ wl,  const float* __restrict__ bl,
    float* __restrict__ out, int n)
{
    extern __shared__ float dsm[];
    float* sW = dsm + E_OFF_W;
    float (*buf0)[ROWP] = (float(*)[ROWP])(dsm + E_OFF_B0);
    float* sb  = dsm + E_OFF_SB;
    float* swl = dsm + E_OFF_WL;
    float* sbl = dsm + E_OFF_BL;
    int*   sId = (int*)(dsm + E_OFF_ID);

    const int e    = blockIdx.y;
    const int cnt  = g_cnt[e];
    const int base = blockIdx.x * TILE;
    if (base >= cnt) return;
    int nrows = cnt - base; if (nrows > TILE) nrows = TILE;
    const int tid = threadIdx.x;

    if (tid < nrows) sId[tid] = g_list[(size_t)e * NPTS_MAX + base + tid];
    __syncthreads();

    // coalesced gather of feature rows into smem
    {
        const int lane = tid & 31, w = tid >> 5;
        for (int r = w; r < nrows; r += TILE / 32) {
            const float* src = &g_feat[(size_t)sId[r] * GF];
            buf0[r][lane]      = src[lane];
            buf0[r][lane + 32] = src[lane + 32];
        }
    }
    __syncthreads();

    // pull this thread's row into registers (buf0[tid] becomes private staging)
    float a[GF];
    if (tid < nrows) {
#pragma unroll
        for (int k = 0; k < GF; k += 4) {
            float4 v = *(const float4*)&buf0[tid][k];
            a[k+0] = v.x; a[k+1] = v.y; a[k+2] = v.z; a[k+3] = v.w;
        }
    }

#pragma unroll 1
    for (int layer = 0; layer < 3; layer++) {
        const float* wp; const float* bp; float freq;
        if (layer == 0) {
            wp = we0 + (size_t)e * GF * GF;
            bp = be0 + e * GF;
            freq = 22.5f + 45.0f * (float)e;        // W0S[e]
        } else {
            wp = wm + ((size_t)(layer - 1) * EXP_N + e) * GF * GF;
            bp = bm + ((size_t)(layer - 1) * EXP_N + e) * GF;
            freq = 30.0f;
        }
        __syncthreads();   // prior layer done reading sW
        for (int i = tid; i < GF * GF; i += TILE) sW[i] = wp[i];
        if (tid < GF) sb[tid] = bp[tid];
        __syncthreads();

        if (tid < nrows)
            layer64(sW, sb, a, buf0[tid], freq);
    }

    __syncthreads();
    if (tid < GF) swl[tid] = wl[e * GF + tid];
    if (tid == 0) sbl[0] = bl[e];
    __syncthreads();

    if (tid < nrows) {
        float acc = sbl[0];
#pragma unroll
        for (int j = 0; j < GF; j++) acc += swl[j] * a[j];
        atomicAdd(&out[sId[tid]], acc);
    }
}

__global__ void aux_kernel(float* __restrict__ out, int n, int out_size)
{
    if (threadIdx.x == 0 && blockIdx.x == 0) {
        long long s = 0;
#pragma unroll
        for (int e = 0; e < EXP_N; e++) {
            long long c = (long long)g_cnt[e];
            s += c * c;
        }
        double aux = (double)EXP_N * (double)s / ((double)n * (double)n);
        if (out_size > n) out[n] = (float)aux;
    }
    // re-zero counters for the next (graph-replayed) iteration
    if (blockIdx.x == 0 && threadIdx.x < EXP_N) g_cnt[threadIdx.x] = 0;
}

// ---------------- launcher ----------------
extern "C" void kernel_launch(void* const* d_in, const int* in_sizes, int n_in,
                              void* d_out, int out_size)
{
    const float* coords = (const float*)d_in[0];
    const float* fw   = (const float*)d_in[1];
    const float* fb   = (const float*)d_in[2];
    const float* gw1  = (const float*)d_in[3];
    const float* gb1  = (const float*)d_in[4];
    const float* ln_g = (const float*)d_in[5];
    const float* ln_b = (const float*)d_in[6];
    const float* gw2  = (const float*)d_in[7];
    const float* gb2  = (const float*)d_in[8];
    const float* we0  = (const float*)d_in[9];
    const float* be0  = (const float*)d_in[10];
    const float* wm   = (const float*)d_in[11];
    const float* bm   = (const float*)d_in[12];
    const float* wl   = (const float*)d_in[13];
    const float* bl   = (const float*)d_in[14];
    float* out = (float*)d_out;

    const int n = in_sizes[0] / 3;
    const int ntiles = (n + TILE - 1) / TILE;

    cudaFuncSetAttribute(gate_kernel,   cudaFuncAttributeMaxDynamicSharedMemorySize, G_SMEM_BYTES);
    cudaFuncSetAttribute(expert_kernel, cudaFuncAttributeMaxDynamicSharedMemorySize, E_SMEM_BYTES);

    gate_kernel<<<ntiles, TILE, G_SMEM_BYTES>>>(coords, fw, fb, gw1, gb1,
                                                ln_g, ln_b, gw2, gb2, out, n);

    dim3 eg(ntiles, EXP_N);
    expert_kernel<<<eg, TILE, E_SMEM_BYTES>>>(we0, be0, wm, bm, wl, bl, out, n);

    aux_kernel<<<1, 32>>>(out, n, out_size);
}

// round 4
// speedup vs baseline: 1.3210x; 1.1531x over previous
#include <cuda_runtime.h>
#include <cstdint>
#include <cstddef>

#define GF      64
#define EXP_N   8
#define TILE    128         // gate tile (threads = points per block)
#define ROWP    68
#define NPTS_MAX 262144

// expert GEMM tiling
#define TR      128         // rows (points) per expert block
#define ETHREADS 256        // 32 row-groups x 8 col-groups
#define RP      68          // A tile pitch (floats)
#define WP      68          // W tile pitch (floats)

// ---------------- scratch (no allocations allowed) ----------------
__device__ float g_feat[(size_t)NPTS_MAX * GF];       // gated features [N,64]
__device__ int   g_list[(size_t)EXP_N * NPTS_MAX];    // per-expert point lists
__device__ int   g_cnt[EXP_N];                        // zeroed at end of aux each iteration

// ---------------- gate smem layout ----------------
#define G_OFF_W    0
#define G_OFF_A    (G_OFF_W + GF*GF)
#define G_OFF_FW   (G_OFF_A + TILE*ROWP)
#define G_OFF_FB   (G_OFF_FW + GF*3)
#define G_OFF_GB1  (G_OFF_FB + GF)
#define G_OFF_LNG  (G_OFF_GB1 + GF)
#define G_OFF_LNB  (G_OFF_LNG + GF)
#define G_OFF_GW2  (G_OFF_LNB + GF)
#define G_OFF_GB2  (G_OFF_GW2 + EXP_N*GF)
#define G_SMEM_FLOATS (G_OFF_GB2 + EXP_N)
#define G_SMEM_BYTES  (G_SMEM_FLOATS * 4)

// ---------------- expert smem layout ----------------
#define E_OFF_A    0                        // A tile [TR][RP]
#define E_OFF_W    (E_OFF_A + TR*RP)        // W tile [64][WP]
#define E_OFF_SB   (E_OFF_W + GF*WP)
#define E_OFF_WL   (E_OFF_SB + GF)
#define E_OFF_BL   (E_OFF_WL + GF)
#define E_OFF_ID   (E_OFF_BL + 1)
#define E_SMEM_FLOATS (E_OFF_ID + TR)
#define E_SMEM_BYTES  (E_SMEM_FLOATS * 4)

// ---------------- gate helpers (unchanged from R3) ----------------
__device__ __forceinline__ void matvec64_stage(const float* __restrict__ sW,
                                               const float* __restrict__ bias,
                                               const float* __restrict__ a,
                                               float* __restrict__ srow)
{
#pragma unroll
    for (int k = 0; k < GF; k += 4) {
        float a0 = bias[k + 0];
        float a1 = bias[k + 1];
        float a2 = bias[k + 2];
        float a3 = bias[k + 3];
        const float4* w0 = (const float4*)&sW[(k + 0) * GF];
        const float4* w1 = (const float4*)&sW[(k + 1) * GF];
        const float4* w2 = (const float4*)&sW[(k + 2) * GF];
        const float4* w3 = (const float4*)&sW[(k + 3) * GF];
#pragma unroll
        for (int j = 0; j < GF / 4; j++) {
            const float x0 = a[4*j], x1 = a[4*j+1], x2 = a[4*j+2], x3 = a[4*j+3];
            float4 q;
            q = w0[j]; a0 = fmaf(x0,q.x, fmaf(x1,q.y, fmaf(x2,q.z, fmaf(x3,q.w, a0))));
            q = w1[j]; a1 = fmaf(x0,q.x, fmaf(x1,q.y, fmaf(x2,q.z, fmaf(x3,q.w, a1))));
            q = w2[j]; a2 = fmaf(x0,q.x, fmaf(x1,q.y, fmaf(x2,q.z, fmaf(x3,q.w, a2))));
            q = w3[j]; a3 = fmaf(x0,q.x, fmaf(x1,q.y, fmaf(x2,q.z, fmaf(x3,q.w, a3))));
        }
        float4 r; r.x = a0; r.y = a1; r.z = a2; r.w = a3;
        *(float4*)&srow[k] = r;
    }
}

// ---------------- kernels ----------------
__global__ void __launch_bounds__(TILE, 3) gate_kernel(
    const float* __restrict__ coords, const float* __restrict__ fw,
    const float* __restrict__ fb,     const float* __restrict__ gw1,
    const float* __restrict__ gb1,    const float* __restrict__ lng,
    const float* __restrict__ lnb,    const float* __restrict__ gw2,
    const float* __restrict__ gb2,    float* __restrict__ out, int n)
{
    extern __shared__ float dsm[];
    float* sW   = dsm + G_OFF_W;
    float (*sA)[ROWP] = (float(*)[ROWP])(dsm + G_OFF_A);
    float* sfw  = dsm + G_OFF_FW;
    float* sfb  = dsm + G_OFF_FB;
    float* sgb1 = dsm + G_OFF_GB1;
    float* slng = dsm + G_OFF_LNG;
    float* slnb = dsm + G_OFF_LNB;
    float* sgw2 = dsm + G_OFF_GW2;
    float* sgb2 = dsm + G_OFF_GB2;

    const int tid  = threadIdx.x;
    const int base = blockIdx.x * TILE;

    for (int i = tid; i < GF * GF; i += TILE) sW[i] = gw1[i];
    for (int i = tid; i < GF * 3;  i += TILE) sfw[i] = fw[i];
    for (int i = tid; i < GF;      i += TILE) {
        sfb[i]  = fb[i];  sgb1[i] = gb1[i];
        slng[i] = lng[i]; slnb[i] = lnb[i];
    }
    for (int i = tid; i < EXP_N * GF; i += TILE) sgw2[i] = gw2[i];
    if (tid < EXP_N) sgb2[tid] = gb2[tid];

    const int p   = base + tid;
    const bool act = (p < n);
    float c0 = 0.f, c1 = 0.f, c2 = 0.f;
    if (act) { c0 = coords[3*p]; c1 = coords[3*p+1]; c2 = coords[3*p+2]; }
    if (act) out[p] = 0.0f;
    __syncthreads();

    float a[GF];
#pragma unroll
    for (int k = 0; k < GF; k++) {
        a[k] = sfb[k] + c0*sfw[3*k] + c1*sfw[3*k+1] + c2*sfw[3*k+2];
        sA[tid][k] = a[k];
    }
    __syncthreads();

    {
        int nrows = n - base; if (nrows > TILE) nrows = TILE;
        if (nrows > 0) {
            for (int idx = tid; idx < nrows * GF; idx += TILE) {
                int r = idx >> 6, k = idx & 63;
                g_feat[(size_t)base * GF + idx] = sA[r][k];
            }
        }
    }
    __syncthreads();

    matvec64_stage(sW, sgb1, a, sA[tid]);

#pragma unroll
    for (int k = 0; k < GF; k += 4) {
        float4 v = *(const float4*)&sA[tid][k];
        a[k+0] = v.x; a[k+1] = v.y; a[k+2] = v.z; a[k+3] = v.w;
    }
    float mu = 0.f;
#pragma unroll
    for (int j = 0; j < GF; j++) mu += a[j];
    mu *= (1.0f / GF);
    float var = 0.f;
#pragma unroll
    for (int j = 0; j < GF; j++) { float d = a[j] - mu; var += d * d; }
    var *= (1.0f / GF);
    const float inv = rsqrtf(var + 1e-5f);
#pragma unroll
    for (int j = 0; j < GF; j++)
        a[j] = (a[j] - mu) * inv * slng[j] + slnb[j];

    float lg[EXP_N];
#pragma unroll
    for (int e = 0; e < EXP_N; e++) {
        float acc = sgb2[e];
#pragma unroll
        for (int j = 0; j < GF; j++) acc += sgw2[e * GF + j] * a[j];
        lg[e] = acc;
    }
    float m1 = -1e30f, m2 = -1e30f;
#pragma unroll
    for (int e = 0; e < EXP_N; e++) {
        float v = lg[e];
        if (v > m1)      { m2 = m1; m1 = v; }
        else if (v > m2) { m2 = v; }
    }

    const int lane = tid & 31;
#pragma unroll
    for (int e = 0; e < EXP_N; e++) {
        bool sel = act && (lg[e] >= m2);
        unsigned bm = __ballot_sync(0xffffffffu, sel);
        if (bm) {
            int leader = __ffs(bm) - 1;
            int pos = 0;
            if (lane == leader) pos = atomicAdd(&g_cnt[e], __popc(bm));
            pos = __shfl_sync(0xffffffffu, pos, leader);
            if (sel) {
                int off = pos + __popc(bm & ((1u << lane) - 1u));
                g_list[(size_t)e * NPTS_MAX + off] = p;
            }
        }
    }
}

// ---------------- expert kernel: register-tiled GEMM ----------------
// 256 threads; thread tile = 4 rows x 8 cols (cols c = colg + 8*i, conflict-free W reads)
__global__ void __launch_bounds__(ETHREADS, 2) expert_kernel(
    const float* __restrict__ we0, const float* __restrict__ be0,
    const float* __restrict__ wm,  const float* __restrict__ bm,
    const float* __restrict__ wl,  const float* __restrict__ bl,
    float* __restrict__ out, int n)
{
    extern __shared__ float dsm[];
    float* sA  = dsm + E_OFF_A;      // [TR][RP]
    float* sW  = dsm + E_OFF_W;      // [64][WP]
    float* sb  = dsm + E_OFF_SB;
    float* swl = dsm + E_OFF_WL;
    float* sbl = dsm + E_OFF_BL;
    int*   sId = (int*)(dsm + E_OFF_ID);

    const int e    = blockIdx.y;
    const int cnt  = g_cnt[e];
    const int base = blockIdx.x * TR;
    if (base >= cnt) return;
    int nrows = cnt - base; if (nrows > TR) nrows = TR;
    const int tid = threadIdx.x;

    for (int i = tid; i < TR; i += ETHREADS)
        sId[i] = (i < nrows) ? g_list[(size_t)e * NPTS_MAX + base + i] : 0;
    __syncthreads();

    // gather A tile (coalesced global reads; conflict-free STS)
    for (int i = tid; i < TR * GF; i += ETHREADS) {
        int r = i >> 6, k = i & 63;
        sA[r * RP + k] = (r < nrows) ? g_feat[(size_t)sId[r] * GF + k] : 0.0f;
    }

    const int colg = tid & 7;        // 0..7
    const int rowg = tid >> 3;       // 0..31
    const int r0   = rowg * 4;

#pragma unroll 1
    for (int layer = 0; layer < 3; layer++) {
        const float* wp; const float* bp; float freq;
        if (layer == 0) {
            wp = we0 + (size_t)e * GF * GF;
            bp = be0 + e * GF;
            freq = 22.5f + 45.0f * (float)e;        // W0S[e]
        } else {
            wp = wm + ((size_t)(layer - 1) * EXP_N + e) * GF * GF;
            bp = bm + ((size_t)(layer - 1) * EXP_N + e) * GF;
            freq = 30.0f;
        }
        __syncthreads();   // previous layer's sW consumers + sA writers done
        for (int i = tid; i < GF * GF; i += ETHREADS) {
            int c = i >> 6, k = i & 63;
            sW[c * WP + k] = wp[i];
        }
        if (tid < GF) sb[tid] = bp[tid];
        __syncthreads();

        float acc[4][8];
#pragma unroll
        for (int i = 0; i < 8; i++) {
            float b = sb[colg + 8 * i];
#pragma unroll
            for (int j = 0; j < 4; j++) acc[j][i] = b;
        }

#pragma unroll
        for (int k = 0; k < GF; k += 4) {
            float4 a0 = *(const float4*)&sA[(r0 + 0) * RP + k];
            float4 a1 = *(const float4*)&sA[(r0 + 1) * RP + k];
            float4 a2 = *(const float4*)&sA[(r0 + 2) * RP + k];
            float4 a3 = *(const float4*)&sA[(r0 + 3) * RP + k];
#pragma unroll
            for (int i = 0; i < 8; i++) {
                float4 w = *(const float4*)&sW[(colg + 8 * i) * WP + k];
                acc[0][i] = fmaf(a0.x,w.x, fmaf(a0.y,w.y, fmaf(a0.z,w.z, fmaf(a0.w,w.w, acc[0][i]))));
                acc[1][i] = fmaf(a1.x,w.x, fmaf(a1.y,w.y, fmaf(a1.z,w.z, fmaf(a1.w,w.w, acc[1][i]))));
                acc[2][i] = fmaf(a2.x,w.x, fmaf(a2.y,w.y, fmaf(a2.z,w.z, fmaf(a2.w,w.w, acc[2][i]))));
                acc[3][i] = fmaf(a3.x,w.x, fmaf(a3.y,w.y, fmaf(a3.z,w.z, fmaf(a3.w,w.w, acc[3][i]))));
            }
        }
        __syncthreads();   // everyone done reading sA for this layer

        // sin epilogue, write activations back into sA for next layer
#pragma unroll
        for (int j = 0; j < 4; j++) {
#pragma unroll
            for (int i = 0; i < 8; i++) {
                sA[(r0 + j) * RP + colg + 8 * i] = __sinf(freq * acc[j][i]);
            }
        }
    }

    __syncthreads();
    if (tid < GF) swl[tid] = wl[e * GF + tid];
    if (tid == 0) sbl[0] = bl[e];
    __syncthreads();

    // final dot per row
    if (tid < TR && tid < nrows) {
        float acc = sbl[0];
        const float* arow = &sA[tid * RP];
#pragma unroll
        for (int j = 0; j < GF; j++) acc += swl[j] * arow[j];
        atomicAdd(&out[sId[tid]], acc);
    }
}

__global__ void aux_kernel(float* __restrict__ out, int n, int out_size)
{
    if (threadIdx.x == 0 && blockIdx.x == 0) {
        long long s = 0;
#pragma unroll
        for (int e = 0; e < EXP_N; e++) {
            long long c = (long long)g_cnt[e];
            s += c * c;
        }
        double aux = (double)EXP_N * (double)s / ((double)n * (double)n);
        if (out_size > n) out[n] = (float)aux;
    }
    if (blockIdx.x == 0 && threadIdx.x < EXP_N) g_cnt[threadIdx.x] = 0;
}

// ---------------- launcher ----------------
extern "C" void kernel_launch(void* const* d_in, const int* in_sizes, int n_in,
                              void* d_out, int out_size)
{
    const float* coords = (const float*)d_in[0];
    const float* fw   = (const float*)d_in[1];
    const float* fb   = (const float*)d_in[2];
    const float* gw1  = (const float*)d_in[3];
    const float* gb1  = (const float*)d_in[4];
    const float* ln_g = (const float*)d_in[5];
    const float* ln_b = (const float*)d_in[6];
    const float* gw2  = (const float*)d_in[7];
    const float* gb2  = (const float*)d_in[8];
    const float* we0  = (const float*)d_in[9];
    const float* be0  = (const float*)d_in[10];
    const float* wm   = (const float*)d_in[11];
    const float* bm   = (const float*)d_in[12];
    const float* wl   = (const float*)d_in[13];
    const float* bl   = (const float*)d_in[14];
    float* out = (float*)d_out;

    const int n = in_sizes[0] / 3;
    const int ntiles = (n + TILE - 1) / TILE;
    const int etiles = (n + TR - 1) / TR;

    cudaFuncSetAttribute(gate_kernel,   cudaFuncAttributeMaxDynamicSharedMemorySize, G_SMEM_BYTES);
    cudaFuncSetAttribute(expert_kernel, cudaFuncAttributeMaxDynamicSharedMemorySize, E_SMEM_BYTES);

    gate_kernel<<<ntiles, TILE, G_SMEM_BYTES>>>(coords, fw, fb, gw1, gb1,
                                                ln_g, ln_b, gw2, gb2, out, n);

    dim3 eg(etiles, EXP_N);
    expert_kernel<<<eg, ETHREADS, E_SMEM_BYTES>>>(we0, be0, wm, bm, wl, bl, out, n);

    aux_kernel<<<1, 32>>>(out, n, out_size);
}

// round 7
// speedup vs baseline: 1.4126x; 1.0693x over previous
#include <cuda_runtime.h>
#include <cstdint>
#include <cstddef>

#define GF      64
#define EXP_N   8
#define NPTS_MAX 262144

#define TR      128         // rows (points) per block (gate & expert)
#define NTHREADS 256        // 32 row-groups x 8 col-groups
#define RP      68          // A tile pitch (floats)
#define WP      68          // W tile pitch (floats)

typedef unsigned long long u64;

// ---------------- scratch (no allocations allowed) ----------------
__device__ float g_feat[(size_t)NPTS_MAX * GF];       // gated features [N,64]
__device__ int   g_list[(size_t)EXP_N * NPTS_MAX];    // per-expert point lists
__device__ int   g_cnt[EXP_N];                        // zeroed at end of aux each iteration

// ---------------- packed f32x2 helpers ----------------
__device__ __forceinline__ u64 fma2(u64 a, u64 b, u64 c)
{
    u64 d;
    asm("fma.rn.f32x2 %0, %1, %2, %3;" : "=l"(d) : "l"(a), "l"(b), "l"(c));
    return d;
}
__device__ __forceinline__ float red2(u64 v, float init)
{
    float lo, hi;
    asm("mov.b64 {%0, %1}, %2;" : "=f"(lo), "=f"(hi) : "l"(v));
    return init + lo + hi;
}

// ---------------- 128x64 GEMM mainloop (A[TR][RP], W[64][WP], K-major both) ----------------
// thread tile: 4 rows x 8 cols; acc packed over k-pairs.
__device__ __forceinline__ void gemm_tile(const float* __restrict__ sA,
                                          const float* __restrict__ sW,
                                          int r0, int colg, u64 acc[4][8])
{
#pragma unroll
    for (int j = 0; j < 4; j++)
#pragma unroll
        for (int i = 0; i < 8; i++) acc[j][i] = 0ULL;

#pragma unroll
    for (int k = 0; k < GF; k += 4) {
        ulonglong2 a0 = *(const ulonglong2*)&sA[(r0 + 0) * RP + k];
        ulonglong2 a1 = *(const ulonglong2*)&sA[(r0 + 1) * RP + k];
        ulonglong2 a2 = *(const ulonglong2*)&sA[(r0 + 2) * RP + k];
        ulonglong2 a3 = *(const ulonglong2*)&sA[(r0 + 3) * RP + k];
#pragma unroll
        for (int i = 0; i < 8; i++) {
            ulonglong2 w = *(const ulonglong2*)&sW[(colg + 8 * i) * WP + k];
            acc[0][i] = fma2(a0.x, w.x, acc[0][i]);
            acc[1][i] = fma2(a1.x, w.x, acc[1][i]);
            acc[2][i] = fma2(a2.x, w.x, acc[2][i]);
            acc[3][i] = fma2(a3.x, w.x, acc[3][i]);
            acc[0][i] = fma2(a0.y, w.y, acc[0][i]);
            acc[1][i] = fma2(a1.y, w.y, acc[1][i]);
            acc[2][i] = fma2(a2.y, w.y, acc[2][i]);
            acc[3][i] = fma2(a3.y, w.y, acc[3][i]);
        }
    }
}

// ---------------- gate smem layout ----------------
#define G_OFF_W    0                          // gw1 [64][WP]
#define G_OFF_A    (G_OFF_W + GF*WP)          // A tile [TR][RP]
#define G_OFF_FW   (G_OFF_A + TR*RP)
#define G_OFF_FB   (G_OFF_FW + GF*3)
#define G_OFF_GB1  (G_OFF_FB + GF)
#define G_OFF_LNG  (G_OFF_GB1 + GF)
#define G_OFF_LNB  (G_OFF_LNG + GF)
#define G_OFF_GW2  (G_OFF_LNB + GF)
#define G_OFF_GB2  (G_OFF_GW2 + EXP_N*GF)
#define G_SMEM_FLOATS (G_OFF_GB2 + EXP_N)
#define G_SMEM_BYTES  (G_SMEM_FLOATS * 4)

// ---------------- expert smem layout ----------------
#define E_OFF_A    0                        // A tile [TR][RP]
#define E_OFF_W    (E_OFF_A + TR*RP)        // W tile [64][WP]
#define E_OFF_SB   (E_OFF_W + GF*WP)
#define E_OFF_WL   (E_OFF_SB + GF)
#define E_OFF_BL   (E_OFF_WL + GF)
#define E_OFF_ID   (E_OFF_BL + 1)
#define E_SMEM_FLOATS (E_OFF_ID + TR)
#define E_SMEM_BYTES  (E_SMEM_FLOATS * 4)

// ---------------- gate kernel ----------------
__global__ void __launch_bounds__(NTHREADS, 2) gate_kernel(
    const float* __restrict__ coords, const float* __restrict__ fw,
    const float* __restrict__ fb,     const float* __restrict__ gw1,
    const float* __restrict__ gb1,    const float* __restrict__ lng,
    const float* __restrict__ lnb,    const float* __restrict__ gw2,
    const float* __restrict__ gb2,    float* __restrict__ out, int n)
{
    extern __shared__ float dsm[];
    float* sW   = dsm + G_OFF_W;
    float* sA   = dsm + G_OFF_A;
    float* sfw  = dsm + G_OFF_FW;
    float* sfb  = dsm + G_OFF_FB;
    float* sgb1 = dsm + G_OFF_GB1;
    float* slng = dsm + G_OFF_LNG;
    float* slnb = dsm + G_OFF_LNB;
    float* sgw2 = dsm + G_OFF_GW2;
    float* sgb2 = dsm + G_OFF_GB2;

    const int tid  = threadIdx.x;
    const int base = blockIdx.x * TR;
    int nrows = n - base; if (nrows > TR) nrows = TR; if (nrows < 0) nrows = 0;

    // stage weights/consts (gw1 is [out c][in k] row-major = K-major)
    for (int i = tid; i < GF * GF; i += NTHREADS) {
        int c = i >> 6, k = i & 63;
        sW[c * WP + k] = gw1[i];
    }
    for (int i = tid; i < GF * 3;  i += NTHREADS) sfw[i] = fw[i];
    for (int i = tid; i < GF;      i += NTHREADS) {
        sfb[i]  = fb[i];  sgb1[i] = gb1[i];
        slng[i] = lng[i]; slnb[i] = lnb[i];
    }
    for (int i = tid; i < EXP_N * GF; i += NTHREADS) sgw2[i] = gw2[i];
    if (tid < EXP_N) sgb2[tid] = gb2[tid];

    // feature rows: thread t < TR computes point base+t
    const int p   = base + tid;
    const bool act = (tid < TR) && (p < n);
    if (act) {
        const float c0 = coords[3*p], c1 = coords[3*p+1], c2 = coords[3*p+2];
        out[p] = 0.0f;                       // fused init
        __syncthreads();                     // sfw/sfb staged
#pragma unroll
        for (int k = 0; k < GF; k++)
            sA[tid * RP + k] = sfb[k] + c0*sfw[3*k] + c1*sfw[3*k+1] + c2*sfw[3*k+2];
    } else {
        __syncthreads();
        if (tid < TR) {                      // zero pad rows (keep GEMM finite)
#pragma unroll
            for (int k = 0; k < GF; k++) sA[tid * RP + k] = 0.0f;
        }
    }
    __syncthreads();

    // coalesced feature writeback
    if (nrows > 0) {
        for (int idx = tid; idx < nrows * GF; idx += NTHREADS) {
            int r = idx >> 6, k = idx & 63;
            g_feat[(size_t)base * GF + idx] = sA[r * RP + k];
        }
    }

    // g = A @ gw1^T + gb1   (register-tiled, f32x2)
    const int colg = tid & 7;
    const int r0   = (tid >> 3) * 4;
    u64 acc[4][8];
    gemm_tile(sA, sW, r0, colg, acc);
    __syncthreads();   // all reads of sA done

    // write g back into sA
#pragma unroll
    for (int j = 0; j < 4; j++)
#pragma unroll
        for (int i = 0; i < 8; i++) {
            int c = colg + 8 * i;
            sA[(r0 + j) * RP + c] = red2(acc[j][i], sgb1[c]);
        }
    __syncthreads();

    if (act) {
        // reload row (conflict-free float4), LayerNorm
        float a[GF];
#pragma unroll
        for (int k = 0; k < GF; k += 4) {
            float4 v = *(const float4*)&sA[tid * RP + k];
            a[k+0] = v.x; a[k+1] = v.y; a[k+2] = v.z; a[k+3] = v.w;
        }
        float mu = 0.f;
#pragma unroll
        for (int j = 0; j < GF; j++) mu += a[j];
        mu *= (1.0f / GF);
        float var = 0.f;
#pragma unroll
        for (int j = 0; j < GF; j++) { float d = a[j] - mu; var += d * d; }
        var *= (1.0f / GF);
        const float inv = rsqrtf(var + 1e-5f);
#pragma unroll
        for (int j = 0; j < GF; j++)
            a[j] = (a[j] - mu) * inv * slng[j] + slnb[j];

        // logits + top-2 on logits (softmax monotonic)
        float lg[EXP_N];
#pragma unroll
        for (int e = 0; e < EXP_N; e++) {
            float accv = sgb2[e];
#pragma unroll
            for (int j = 0; j < GF; j++) accv += sgw2[e * GF + j] * a[j];
            lg[e] = accv;
        }
        float m1 = -1e30f, m2 = -1e30f;
#pragma unroll
        for (int e = 0; e < EXP_N; e++) {
            float v = lg[e];
            if (v > m1)      { m2 = m1; m1 = v; }
            else if (v > m2) { m2 = v; }
        }
        const int lane = tid & 31;
#pragma unroll
        for (int e = 0; e < EXP_N; e++) {
            bool sel = (lg[e] >= m2);
            unsigned bm = __ballot_sync(0xffffffffu, sel);   // tid<TR ⇒ full warps 0..3
            if (bm) {
                int leader = __ffs(bm) - 1;
                int pos = 0;
                if (lane == leader) pos = atomicAdd(&g_cnt[e], __popc(bm));
                pos = __shfl_sync(0xffffffffu, pos, leader);
                if (sel) {
                    int off = pos + __popc(bm & ((1u << lane) - 1u));
                    g_list[(size_t)e * NPTS_MAX + off] = p;
                }
            }
        }
    }
}

// ---------------- expert kernel ----------------
__global__ void __launch_bounds__(NTHREADS, 2) expert_kernel(
    const float* __restrict__ we0, const float* __restrict__ be0,
    const float* __restrict__ wm,  const float* __restrict__ bm,
    const float* __restrict__ wl,  const float* __restrict__ bl,
    float* __restrict__ out, int n)
{
    extern __shared__ float dsm[];
    float* sA  = dsm + E_OFF_A;
    float* sW  = dsm + E_OFF_W;
    float* sb  = dsm + E_OFF_SB;
    float* swl = dsm + E_OFF_WL;
    float* sbl = dsm + E_OFF_BL;
    int*   sId = (int*)(dsm + E_OFF_ID);

    const int e    = blockIdx.y;
    const int cnt  = g_cnt[e];
    const int base = blockIdx.x * TR;
    if (base >= cnt) return;
    int nrows = cnt - base; if (nrows > TR) nrows = TR;
    const int tid = threadIdx.x;

    for (int i = tid; i < TR; i += NTHREADS)
        sId[i] = (i < nrows) ? g_list[(size_t)e * NPTS_MAX + base + i] : 0;
    __syncthreads();

    for (int i = tid; i < TR * GF; i += NTHREADS) {
        int r = i >> 6, k = i & 63;
        sA[r * RP + k] = (r < nrows) ? g_feat[(size_t)sId[r] * GF + k] : 0.0f;
    }

    const int colg = tid & 7;
    const int r0   = (tid >> 3) * 4;

#pragma unroll 1
    for (int layer = 0; layer < 3; layer++) {
        const float* wp; const float* bp; float freq;
        if (layer == 0) {
            wp = we0 + (size_t)e * GF * GF;
            bp = be0 + e * GF;
            freq = 22.5f + 45.0f * (float)e;        // W0S[e]
        } else {
            wp = wm + ((size_t)(layer - 1) * EXP_N + e) * GF * GF;
            bp = bm + ((size_t)(layer - 1) * EXP_N + e) * GF;
            freq = 30.0f;
        }
        __syncthreads();
        for (int i = tid; i < GF * GF; i += NTHREADS) {
            int c = i >> 6, k = i & 63;
            sW[c * WP + k] = wp[i];
        }
        if (tid < GF) sb[tid] = bp[tid];
        __syncthreads();

        u64 acc[4][8];
        gemm_tile(sA, sW, r0, colg, acc);
        __syncthreads();   // everyone done reading sA

        // sin epilogue back into sA
#pragma unroll
        for (int j = 0; j < 4; j++)
#pragma unroll
            for (int i = 0; i < 8; i++) {
                int c = colg + 8 * i;
                sA[(r0 + j) * RP + c] = __sinf(freq * red2(acc[j][i], sb[c]));
            }
    }

    __syncthreads();
    if (tid < GF) swl[tid] = wl[e * GF + tid];
    if (tid == 0) sbl[0] = bl[e];
    __syncthreads();

    if (tid < TR && tid < nrows) {
        float accv = sbl[0];
#pragma unroll
        for (int k = 0; k < GF; k += 4) {
            float4 v = *(const float4*)&sA[tid * RP + k];
            accv += swl[k]*v.x + swl[k+1]*v.y + swl[k+2]*v.z + swl[k+3]*v.w;
        }
        atomicAdd(&out[sId[tid]], accv);
    }
}

__global__ void aux_kernel(float* __restrict__ out, int n, int out_size)
{
    if (threadIdx.x == 0 && blockIdx.x == 0) {
        long long s = 0;
#pragma unroll
        for (int e = 0; e < EXP_N; e++) {
            long long c = (long long)g_cnt[e];
            s += c * c;
        }
        double aux = (double)EXP_N * (double)s / ((double)n * (double)n);
        if (out_size > n) out[n] = (float)aux;
    }
    if (blockIdx.x == 0 && threadIdx.x < EXP_N) g_cnt[threadIdx.x] = 0;
}

// ---------------- launcher ----------------
extern "C" void kernel_launch(void* const* d_in, const int* in_sizes, int n_in,
                              void* d_out, int out_size)
{
    const float* coords = (const float*)d_in[0];
    const float* fw   = (const float*)d_in[1];
    const float* fb   = (const float*)d_in[2];
    const float* gw1  = (const float*)d_in[3];
    const float* gb1  = (const float*)d_in[4];
    const float* ln_g = (const float*)d_in[5];
    const float* ln_b = (const float*)d_in[6];
    const float* gw2  = (const float*)d_in[7];
    const float* gb2  = (const float*)d_in[8];
    const float* we0  = (const float*)d_in[9];
    const float* be0  = (const float*)d_in[10];
    const float* wm   = (const float*)d_in[11];
    const float* bm   = (const float*)d_in[12];
    const float* wl   = (const float*)d_in[13];
    const float* bl   = (const float*)d_in[14];
    float* out = (float*)d_out;

    const int n = in_sizes[0] / 3;
    const int ntiles = (n + TR - 1) / TR;

    cudaFuncSetAttribute(gate_kernel,   cudaFuncAttributeMaxDynamicSharedMemorySize, G_SMEM_BYTES);
    cudaFuncSetAttribute(expert_kernel, cudaFuncAttributeMaxDynamicSharedMemorySize, E_SMEM_BYTES);

    gate_kernel<<<ntiles, NTHREADS, G_SMEM_BYTES>>>(coords, fw, fb, gw1, gb1,
                                                    ln_g, ln_b, gw2, gb2, out, n);

    dim3 eg(ntiles, EXP_N);
    expert_kernel<<<eg, NTHREADS, E_SMEM_BYTES>>>(we0, be0, wm, bm, wl, bl, out, n);

    aux_kernel<<<1, 32>>>(out, n, out_size);
}

// round 9
// speedup vs baseline: 1.4233x; 1.0076x over previous
#include <cuda_runtime.h>
#include <cstdint>
#include <cstddef>

#define GF      64
#define EXP_N   8
#define NPTS_MAX 262144

#define TR      128         // rows (points) per block (gate & expert)
#define NTHREADS 256        // 32 row-groups x 8 col-groups
#define RP      68          // A tile row pitch (floats); 272B = 17*16 -> 16B-aligned rows
#define WP      68          // W tile row pitch (floats)

// XOR chunk swizzle: element (r,k) -> r*RP + ((k/4 ^ s(r))*4) + k%4, s(r)=(r>>2)&3.
// Stays within the row (no overlap); de-conflicts the 4-row strided mainloop loads.
#define SROW(r)   (((r) >> 2) & 3)
#define AIDX(r,k) ((r) * RP + ((((k) >> 2) ^ SROW(r)) << 2) + ((k) & 3))
#define A_TILE_FLOATS (TR * RP)

typedef unsigned long long u64;

// ---------------- scratch (no allocations allowed) ----------------
__device__ float g_feat[(size_t)NPTS_MAX * GF];       // gated features [N,64]
__device__ int   g_list[(size_t)EXP_N * NPTS_MAX];    // per-expert point lists
__device__ int   g_cnt[EXP_N];                        // zeroed at end of aux each iteration

// ---------------- packed f32x2 helpers ----------------
__device__ __forceinline__ u64 fma2(u64 a, u64 b, u64 c)
{
    u64 d;
    asm("fma.rn.f32x2 %0, %1, %2, %3;" : "=l"(d) : "l"(a), "l"(b), "l"(c));
    return d;
}
__device__ __forceinline__ float red2(u64 v, float init)
{
    float lo, hi;
    asm("mov.b64 {%0, %1}, %2;" : "=f"(lo), "=f"(hi) : "l"(v));
    return init + lo + hi;
}

// ---------------- 128x64 GEMM mainloop (A chunk-swizzled, W[64][WP], K-major) ----------------
__device__ __forceinline__ void gemm_tile(const float* __restrict__ sA,
                                          const float* __restrict__ sW,
                                          int r0, int colg, u64 acc[4][8])
{
#pragma unroll
    for (int j = 0; j < 4; j++)
#pragma unroll
        for (int i = 0; i < 8; i++) acc[j][i] = 0ULL;

    const int sw = SROW(r0);                 // same for r0..r0+3
    const float* __restrict__ row0 = &sA[(r0 + 0) * RP];
    const float* __restrict__ row1 = &sA[(r0 + 1) * RP];
    const float* __restrict__ row2 = &sA[(r0 + 2) * RP];
    const float* __restrict__ row3 = &sA[(r0 + 3) * RP];

#pragma unroll
    for (int k = 0; k < GF; k += 4) {
        const int co = (((k >> 2) ^ sw) << 2);   // swizzled chunk byte-offset (in floats)
        ulonglong2 a0 = *(const ulonglong2*)&row0[co];
        ulonglong2 a1 = *(const ulonglong2*)&row1[co];
        ulonglong2 a2 = *(const ulonglong2*)&row2[co];
        ulonglong2 a3 = *(const ulonglong2*)&row3[co];
#pragma unroll
        for (int i = 0; i < 8; i++) {
            ulonglong2 w = *(const ulonglong2*)&sW[(colg + 8 * i) * WP + k];
            acc[0][i] = fma2(a0.x, w.x, acc[0][i]);
            acc[1][i] = fma2(a1.x, w.x, acc[1][i]);
            acc[2][i] = fma2(a2.x, w.x, acc[2][i]);
            acc[3][i] = fma2(a3.x, w.x, acc[3][i]);
            acc[0][i] = fma2(a0.y, w.y, acc[0][i]);
            acc[1][i] = fma2(a1.y, w.y, acc[1][i]);
            acc[2][i] = fma2(a2.y, w.y, acc[2][i]);
            acc[3][i] = fma2(a3.y, w.y, acc[3][i]);
        }
    }
}

// ---------------- gate smem layout ----------------
#define G_OFF_W    0                          // gw1 [64][WP]
#define G_OFF_A    (G_OFF_W + GF*WP)          // A tile (chunk-swizzled)
#define G_OFF_CRD  (G_OFF_A + A_TILE_FLOATS)  // coords [TR*3]
#define G_OFF_FW   (G_OFF_CRD + TR*3)
#define G_OFF_FB   (G_OFF_FW + GF*3)
#define G_OFF_GB1  (G_OFF_FB + GF)
#define G_OFF_LNG  (G_OFF_GB1 + GF)
#define G_OFF_LNB  (G_OFF_LNG + GF)
#define G_OFF_GW2  (G_OFF_LNB + GF)
#define G_OFF_GB2  (G_OFF_GW2 + EXP_N*GF)
#define G_SMEM_FLOATS (G_OFF_GB2 + EXP_N)
#define G_SMEM_BYTES  (G_SMEM_FLOATS * 4)

// ---------------- expert smem layout ----------------
#define E_OFF_A    0                        // A tile (chunk-swizzled)
#define E_OFF_W    (E_OFF_A + A_TILE_FLOATS)
#define E_OFF_SB   (E_OFF_W + GF*WP)
#define E_OFF_WL   (E_OFF_SB + GF)
#define E_OFF_BL   (E_OFF_WL + GF)
#define E_OFF_ID   (E_OFF_BL + 1)
#define E_SMEM_FLOATS (E_OFF_ID + TR)
#define E_SMEM_BYTES  (E_SMEM_FLOATS * 4)

// ---------------- gate kernel ----------------
__global__ void __launch_bounds__(NTHREADS, 2) gate_kernel(
    const float* __restrict__ coords, const float* __restrict__ fw,
    const float* __restrict__ fb,     const float* __restrict__ gw1,
    const float* __restrict__ gb1,    const float* __restrict__ lng,
    const float* __restrict__ lnb,    const float* __restrict__ gw2,
    const float* __restrict__ gb2,    float* __restrict__ out, int n)
{
    extern __shared__ float dsm[];
    float* sW   = dsm + G_OFF_W;
    float* sA   = dsm + G_OFF_A;
    float* scrd = dsm + G_OFF_CRD;
    float* sfw  = dsm + G_OFF_FW;
    float* sfb  = dsm + G_OFF_FB;
    float* sgb1 = dsm + G_OFF_GB1;
    float* slng = dsm + G_OFF_LNG;
    float* slnb = dsm + G_OFF_LNB;
    float* sgw2 = dsm + G_OFF_GW2;
    float* sgb2 = dsm + G_OFF_GB2;

    const int tid  = threadIdx.x;
    const int base = blockIdx.x * TR;
    int nrows = n - base; if (nrows > TR) nrows = TR; if (nrows < 0) nrows = 0;

    // stage weights/consts (gw1 is [out c][in k] row-major = K-major)
    for (int i = tid; i < GF * GF; i += NTHREADS) {
        int c = i >> 6, k = i & 63;
        sW[c * WP + k] = gw1[i];
    }
    for (int i = tid; i < GF * 3;  i += NTHREADS) sfw[i] = fw[i];
    for (int i = tid; i < GF;      i += NTHREADS) {
        sfb[i]  = fb[i];  sgb1[i] = gb1[i];
        slng[i] = lng[i]; slnb[i] = lnb[i];
    }
    for (int i = tid; i < EXP_N * GF; i += NTHREADS) sgw2[i] = gw2[i];
    if (tid < EXP_N) sgb2[tid] = gb2[tid];
    for (int i = tid; i < nrows * 3; i += NTHREADS) scrd[i] = coords[(size_t)base * 3 + i];
    if (tid < nrows) out[base + tid] = 0.0f;          // fused init
    __syncthreads();

    // feature = coords @ fw^T + fb : k-sliced, fused g_feat writeback
    for (int i = tid; i < TR * GF; i += NTHREADS) {
        int r = i >> 6, k = i & 63;
        float v = 0.0f;
        if (r < nrows) {
            v = sfb[k] + scrd[3*r]*sfw[3*k] + scrd[3*r+1]*sfw[3*k+1]
                       + scrd[3*r+2]*sfw[3*k+2];
            g_feat[(size_t)base * GF + i] = v;
        }
        sA[AIDX(r, k)] = v;
    }
    __syncthreads();

    // g = A @ gw1^T + gb1   (register-tiled, f32x2)
    const int colg = tid & 7;
    const int r0   = (tid >> 3) * 4;
    u64 acc[4][8];
    gemm_tile(sA, sW, r0, colg, acc);
    __syncthreads();   // all reads of sA done

    // write g back into sA (conflict-free)
#pragma unroll
    for (int j = 0; j < 4; j++)
#pragma unroll
        for (int i = 0; i < 8; i++) {
            int c = colg + 8 * i;
            sA[AIDX(r0 + j, c)] = red2(acc[j][i], sgb1[c]);
        }
    __syncthreads();

    const int p = base + tid;
    const bool act = (tid < TR) && (p < n);
    if (act) {
        // reload row, LayerNorm
        float a[GF];
        const float* arow = &sA[tid * RP];
        const int sw = SROW(tid);
#pragma unroll
        for (int k = 0; k < GF; k += 4) {
            float4 v = *(const float4*)&arow[(((k >> 2) ^ sw) << 2)];
            a[k+0] = v.x; a[k+1] = v.y; a[k+2] = v.z; a[k+3] = v.w;
        }
        float mu = 0.f;
#pragma unroll
        for (int j = 0; j < GF; j++) mu += a[j];
        mu *= (1.0f / GF);
        float var = 0.f;
#pragma unroll
        for (int j = 0; j < GF; j++) { float d = a[j] - mu; var += d * d; }
        var *= (1.0f / GF);
        const float inv = rsqrtf(var + 1e-5f);
#pragma unroll
        for (int j = 0; j < GF; j++)
            a[j] = (a[j] - mu) * inv * slng[j] + slnb[j];

        // logits + top-2 on logits (softmax monotonic)
        float lg[EXP_N];
#pragma unroll
        for (int e = 0; e < EXP_N; e++) {
            float accv = sgb2[e];
#pragma unroll
            for (int j = 0; j < GF; j++) accv += sgw2[e * GF + j] * a[j];
            lg[e] = accv;
        }
        float m1 = -1e30f, m2 = -1e30f;
#pragma unroll
        for (int e = 0; e < EXP_N; e++) {
            float v = lg[e];
            if (v > m1)      { m2 = m1; m1 = v; }
            else if (v > m2) { m2 = v; }
        }
        const int lane = tid & 31;
#pragma unroll
        for (int e = 0; e < EXP_N; e++) {
            bool sel = (lg[e] >= m2);
            unsigned bm = __ballot_sync(0xffffffffu, sel);   // tid<TR ⇒ full warps 0..3
            if (bm) {
                int leader = __ffs(bm) - 1;
                int pos = 0;
                if (lane == leader) pos = atomicAdd(&g_cnt[e], __popc(bm));
                pos = __shfl_sync(0xffffffffu, pos, leader);
                if (sel) {
                    int off = pos + __popc(bm & ((1u << lane) - 1u));
                    g_list[(size_t)e * NPTS_MAX + off] = p;
                }
            }
        }
    }
}

// ---------------- expert kernel ----------------
__global__ void __launch_bounds__(NTHREADS, 2) expert_kernel(
    const float* __restrict__ we0, const float* __restrict__ be0,
    const float* __restrict__ wm,  const float* __restrict__ bm,
    const float* __restrict__ wl,  const float* __restrict__ bl,
    float* __restrict__ out, int n)
{
    extern __shared__ float dsm[];
    float* sA  = dsm + E_OFF_A;
    float* sW  = dsm + E_OFF_W;
    float* sb  = dsm + E_OFF_SB;
    float* swl = dsm + E_OFF_WL;
    float* sbl = dsm + E_OFF_BL;
    int*   sId = (int*)(dsm + E_OFF_ID);

    const int e    = blockIdx.y;
    const int cnt  = g_cnt[e];
    const int base = blockIdx.x * TR;
    if (base >= cnt) return;
    int nrows = cnt - base; if (nrows > TR) nrows = TR;
    const int tid = threadIdx.x;

    for (int i = tid; i < TR; i += NTHREADS)
        sId[i] = (i < nrows) ? g_list[(size_t)e * NPTS_MAX + base + i] : 0;
    __syncthreads();

    // gather A tile (coalesced LDG; conflict-free STS)
    for (int i = tid; i < TR * GF; i += NTHREADS) {
        int r = i >> 6, k = i & 63;
        sA[AIDX(r, k)] = (r < nrows) ? g_feat[(size_t)sId[r] * GF + k] : 0.0f;
    }

    const int colg = tid & 7;
    const int r0   = (tid >> 3) * 4;

#pragma unroll 1
    for (int layer = 0; layer < 3; layer++) {
        const float* wp; const float* bp; float freq;
        if (layer == 0) {
            wp = we0 + (size_t)e * GF * GF;
            bp = be0 + e * GF;
            freq = 22.5f + 45.0f * (float)e;        // W0S[e]
        } else {
            wp = wm + ((size_t)(layer - 1) * EXP_N + e) * GF * GF;
            bp = bm + ((size_t)(layer - 1) * EXP_N + e) * GF;
            freq = 30.0f;
        }
        __syncthreads();
        for (int i = tid; i < GF * GF; i += NTHREADS) {
            int c = i >> 6, k = i & 63;
            sW[c * WP + k] = wp[i];
        }
        if (tid < GF) sb[tid] = bp[tid];
        __syncthreads();

        u64 acc[4][8];
        gemm_tile(sA, sW, r0, colg, acc);
        __syncthreads();   // everyone done reading sA

        // sin epilogue back into sA (conflict-free stores)
#pragma unroll
        for (int j = 0; j < 4; j++)
#pragma unroll
            for (int i = 0; i < 8; i++) {
                int c = colg + 8 * i;
                sA[AIDX(r0 + j, c)] = __sinf(freq * red2(acc[j][i], sb[c]));
            }
    }

    __syncthreads();
    if (tid < GF) swl[tid] = wl[e * GF + tid];
    if (tid == 0) sbl[0] = bl[e];
    __syncthreads();

    if (tid < TR && tid < nrows) {
        float accv = sbl[0];
        const float* arow = &sA[tid * RP];
        const int sw = SROW(tid);
#pragma unroll
        for (int k = 0; k < GF; k += 4) {
            float4 v = *(const float4*)&arow[(((k >> 2) ^ sw) << 2)];
            accv += swl[k]*v.x + swl[k+1]*v.y + swl[k+2]*v.z + swl[k+3]*v.w;
        }
        atomicAdd(&out[sId[tid]], accv);
    }
}

__global__ void aux_kernel(float* __restrict__ out, int n, int out_size)
{
    if (threadIdx.x == 0 && blockIdx.x == 0) {
        long long s = 0;
#pragma unroll
        for (int e = 0; e < EXP_N; e++) {
            long long c = (long long)g_cnt[e];
            s += c * c;
        }
        double aux = (double)EXP_N * (double)s / ((double)n * (double)n);
        if (out_size > n) out[n] = (float)aux;
    }
    if (blockIdx.x == 0 && threadIdx.x < EXP_N) g_cnt[threadIdx.x] = 0;
}

// ---------------- launcher ----------------
extern "C" void kernel_launch(void* const* d_in, const int* in_sizes, int n_in,
                              void* d_out, int out_size)
{
    const float* coords = (const float*)d_in[0];
    const float* fw   = (const float*)d_in[1];
    const float* fb   = (const float*)d_in[2];
    const float* gw1  = (const float*)d_in[3];
    const float* gb1  = (const float*)d_in[4];
    const float* ln_g = (const float*)d_in[5];
    const float* ln_b = (const float*)d_in[6];
    const float* gw2  = (const float*)d_in[7];
    const float* gb2  = (const float*)d_in[8];
    const float* we0  = (const float*)d_in[9];
    const float* be0  = (const float*)d_in[10];
    const float* wm   = (const float*)d_in[11];
    const float* bm   = (const float*)d_in[12];
    const float* wl   = (const float*)d_in[13];
    const float* bl   = (const float*)d_in[14];
    float* out = (float*)d_out;

    const int n = in_sizes[0] / 3;
    const int ntiles = (n + TR - 1) / TR;

    cudaFuncSetAttribute(gate_kernel,   cudaFuncAttributeMaxDynamicSharedMemorySize, G_SMEM_BYTES);
    cudaFuncSetAttribute(expert_kernel, cudaFuncAttributeMaxDynamicSharedMemorySize, E_SMEM_BYTES);

    gate_kernel<<<ntiles, NTHREADS, G_SMEM_BYTES>>>(coords, fw, fb, gw1, gb1,
                                                    ln_g, ln_b, gw2, gb2, out, n);

    dim3 eg(ntiles, EXP_N);
    expert_kernel<<<eg, NTHREADS, E_SMEM_BYTES>>>(we0, be0, wm, bm, wl, bl, out, n);

    aux_kernel<<<1, 32>>>(out, n, out_size);
}